// round 1
// baseline (speedup 1.0000x reference)
#include <cuda_runtime.h>
#include <cuda_bf16.h>
#include <cstdint>

// Problem constants (fixed by the reference setup)
#define NN 100000
#define EE 3200000
#define DD 128

// ---------------- device scratch (no allocations allowed) ----------------
__device__ int   g_deg[NN];
__device__ int   g_off[NN];
__device__ int   g_cursor[NN];
__device__ int   g_bsum[1024];
__device__ int   g_ecol[EE];
__device__ float g_ew[EE];
__device__ float g_y1[(size_t)NN * DD];   // feat @ W1

// ---------------- small helpers ----------------
__global__ void k_zero_deg() {
    int i = blockIdx.x * blockDim.x + threadIdx.x;
    if (i < NN) g_deg[i] = 0;
}

__global__ void k_hist(const int* __restrict__ rows) {
    int e = blockIdx.x * blockDim.x + threadIdx.x;
    if (e < EE) atomicAdd(&g_deg[rows[e]], 1);
}

// block-level exclusive scan (1024 threads = 32 warps)
__global__ void k_scan_block(const int* __restrict__ in, int* __restrict__ out,
                             int* __restrict__ bsum, int n) {
    __shared__ int warpSums[32];
    int i = blockIdx.x * 1024 + threadIdx.x;
    int lane = threadIdx.x & 31, wid = threadIdx.x >> 5;
    int v = (i < n) ? in[i] : 0;
    int s = v;
    #pragma unroll
    for (int o = 1; o < 32; o <<= 1) {
        int t = __shfl_up_sync(0xffffffffu, s, o);
        if (lane >= o) s += t;
    }
    if (lane == 31) warpSums[wid] = s;
    __syncthreads();
    if (wid == 0) {
        int ws = warpSums[lane];
        #pragma unroll
        for (int o = 1; o < 32; o <<= 1) {
            int t = __shfl_up_sync(0xffffffffu, ws, o);
            if (lane >= o) ws += t;
        }
        warpSums[lane] = ws;
    }
    __syncthreads();
    int excl = s - v + ((wid > 0) ? warpSums[wid - 1] : 0);
    if (i < n) out[i] = excl;
    if (threadIdx.x == 1023 && bsum) bsum[blockIdx.x] = excl + v;
}

__global__ void k_finalize_off() {
    int i = blockIdx.x * blockDim.x + threadIdx.x;
    if (i < NN) {
        int o = g_off[i] + g_bsum[i >> 10];
        g_off[i] = o;
        g_cursor[i] = o;
    }
}

__global__ void k_scatter(const int* __restrict__ rows, const int* __restrict__ cols,
                          const float* __restrict__ vals) {
    int e = blockIdx.x * blockDim.x + threadIdx.x;
    if (e < EE) {
        int r = rows[e];
        int p = atomicAdd(&g_cursor[r], 1);
        g_ecol[p] = cols[e];
        g_ew[p]   = vals[e];
    }
}

// ---------------- dense GEMM: out = X[n,128] @ W[128,128] (+ fused norm epilogue) ----
// block = 256 threads = 8 warps; block tile = 64 rows; warp tile = 8 rows x 128 cols;
// lane owns cols [4*lane, 4*lane+4)
template <bool EPI>
__global__ __launch_bounds__(256) void gemm_kernel(
    const float* __restrict__ X, const float* __restrict__ W,
    const float* __restrict__ b, const float* __restrict__ off,
    const float* __restrict__ sc, float* __restrict__ out, int n)
{
    extern __shared__ float smem[];
    float* sW = smem;               // 128*128
    float* sX = smem + 128 * 128;   // 64*128

    const int warp = threadIdx.x >> 5, lane = threadIdx.x & 31;
    const int rowBase = blockIdx.x * 64;

    // load W (16384 floats = 4096 float4, 16 per thread)
    for (int i = threadIdx.x; i < 128 * 32; i += 256)
        ((float4*)sW)[i] = ((const float4*)W)[i];
    // load X tile (64 rows, zero-pad tail)
    for (int i = threadIdx.x; i < 64 * 32; i += 256) {
        int r = i >> 5, kk = i & 31;
        float4 v = make_float4(0.f, 0.f, 0.f, 0.f);
        int gr = rowBase + r;
        if (gr < n) v = ((const float4*)(X + (size_t)gr * 128))[kk];
        ((float4*)sX)[i] = v;
    }
    __syncthreads();

    float acc[8][4];
    #pragma unroll
    for (int r = 0; r < 8; r++)
        #pragma unroll
        for (int c = 0; c < 4; c++) acc[r][c] = 0.f;

    const float* xbase = sX + (warp * 8) * 128;

    #pragma unroll 1
    for (int k = 0; k < 128; k += 4) {
        float4 wv0 = *(const float4*)(sW + (k + 0) * 128 + 4 * lane);
        float4 wv1 = *(const float4*)(sW + (k + 1) * 128 + 4 * lane);
        float4 wv2 = *(const float4*)(sW + (k + 2) * 128 + 4 * lane);
        float4 wv3 = *(const float4*)(sW + (k + 3) * 128 + 4 * lane);
        #pragma unroll
        for (int r = 0; r < 8; r++) {
            float4 xv = *(const float4*)(xbase + r * 128 + k);
            acc[r][0] = fmaf(xv.x, wv0.x, acc[r][0]);
            acc[r][1] = fmaf(xv.x, wv0.y, acc[r][1]);
            acc[r][2] = fmaf(xv.x, wv0.z, acc[r][2]);
            acc[r][3] = fmaf(xv.x, wv0.w, acc[r][3]);
            acc[r][0] = fmaf(xv.y, wv1.x, acc[r][0]);
            acc[r][1] = fmaf(xv.y, wv1.y, acc[r][1]);
            acc[r][2] = fmaf(xv.y, wv1.z, acc[r][2]);
            acc[r][3] = fmaf(xv.y, wv1.w, acc[r][3]);
            acc[r][0] = fmaf(xv.z, wv2.x, acc[r][0]);
            acc[r][1] = fmaf(xv.z, wv2.y, acc[r][1]);
            acc[r][2] = fmaf(xv.z, wv2.z, acc[r][2]);
            acc[r][3] = fmaf(xv.z, wv2.w, acc[r][3]);
            acc[r][0] = fmaf(xv.w, wv3.x, acc[r][0]);
            acc[r][1] = fmaf(xv.w, wv3.y, acc[r][1]);
            acc[r][2] = fmaf(xv.w, wv3.z, acc[r][2]);
            acc[r][3] = fmaf(xv.w, wv3.w, acc[r][3]);
        }
    }

    const int warpRow = rowBase + warp * 8;
    if (EPI) {
        float4 bv  = *(const float4*)(b  + 4 * lane);
        float4 scv = *(const float4*)(sc + 4 * lane);
        float4 ofv = *(const float4*)(off + 4 * lane);
        #pragma unroll
        for (int r = 0; r < 8; r++) {
            int row = warpRow + r;
            if (row >= n) break;
            float h0 = fmaxf(acc[r][0] + bv.x, 0.f);
            float h1 = fmaxf(acc[r][1] + bv.y, 0.f);
            float h2 = fmaxf(acc[r][2] + bv.z, 0.f);
            float h3 = fmaxf(acc[r][3] + bv.w, 0.f);
            float s = h0 + h1 + h2 + h3;
            #pragma unroll
            for (int o = 16; o; o >>= 1) s += __shfl_xor_sync(0xffffffffu, s, o);
            float mean = s * (1.f / 128.f);
            float d0 = h0 - mean, d1 = h1 - mean, d2 = h2 - mean, d3 = h3 - mean;
            float q = d0 * d0 + d1 * d1 + d2 * d2 + d3 * d3;
            #pragma unroll
            for (int o = 16; o; o >>= 1) q += __shfl_xor_sync(0xffffffffu, q, o);
            float inv = rsqrtf(q * (1.f / 128.f) + 1e-9f);
            float4 o4;
            o4.x = d0 * scv.x * inv + ofv.x;
            o4.y = d1 * scv.y * inv + ofv.y;
            o4.z = d2 * scv.z * inv + ofv.z;
            o4.w = d3 * scv.w * inv + ofv.w;
            *(float4*)(out + (size_t)row * 128 + 4 * lane) = o4;
        }
    } else {
        #pragma unroll
        for (int r = 0; r < 8; r++) {
            int row = warpRow + r;
            if (row >= n) break;
            float4 o4 = make_float4(acc[r][0], acc[r][1], acc[r][2], acc[r][3]);
            *(float4*)(out + (size_t)row * 128 + 4 * lane) = o4;
        }
    }
}

// ---------------- SpMM gather + fused epilogue: out[r] += norm(relu(A@y1 + b1)) ----
__global__ __launch_bounds__(256) void spmm_kernel(
    const float* __restrict__ b, const float* __restrict__ off,
    const float* __restrict__ sc, float* __restrict__ out)
{
    int gw = (blockIdx.x * blockDim.x + threadIdx.x) >> 5;
    if (gw >= NN) return;
    int lane = threadIdx.x & 31;
    int start = g_off[gw];
    int deg   = g_deg[gw];

    float4 acc = make_float4(0.f, 0.f, 0.f, 0.f);
    for (int base = 0; base < deg; base += 32) {
        int idx = base + lane;
        int c = 0; float w = 0.f;
        if (idx < deg) { c = g_ecol[start + idx]; w = g_ew[start + idx]; }
        int m = min(32, deg - base);
        #pragma unroll 4
        for (int j = 0; j < m; j++) {
            int   cj = __shfl_sync(0xffffffffu, c, j);
            float wj = __shfl_sync(0xffffffffu, w, j);
            float4 y = *(const float4*)(g_y1 + (size_t)cj * 128 + 4 * lane);
            acc.x = fmaf(wj, y.x, acc.x);
            acc.y = fmaf(wj, y.y, acc.y);
            acc.z = fmaf(wj, y.z, acc.z);
            acc.w = fmaf(wj, y.w, acc.w);
        }
    }

    float4 bv  = *(const float4*)(b  + 4 * lane);
    float4 scv = *(const float4*)(sc + 4 * lane);
    float4 ofv = *(const float4*)(off + 4 * lane);
    float h0 = fmaxf(acc.x + bv.x, 0.f);
    float h1 = fmaxf(acc.y + bv.y, 0.f);
    float h2 = fmaxf(acc.z + bv.z, 0.f);
    float h3 = fmaxf(acc.w + bv.w, 0.f);
    float s = h0 + h1 + h2 + h3;
    #pragma unroll
    for (int o = 16; o; o >>= 1) s += __shfl_xor_sync(0xffffffffu, s, o);
    float mean = s * (1.f / 128.f);
    float d0 = h0 - mean, d1 = h1 - mean, d2 = h2 - mean, d3 = h3 - mean;
    float q = d0 * d0 + d1 * d1 + d2 * d2 + d3 * d3;
    #pragma unroll
    for (int o = 16; o; o >>= 1) q += __shfl_xor_sync(0xffffffffu, q, o);
    float inv = rsqrtf(q * (1.f / 128.f) + 1e-9f);

    float* orow = out + (size_t)gw * 128 + 4 * lane;
    float4 prev = *(float4*)orow;
    float4 o4;
    o4.x = prev.x + d0 * scv.x * inv + ofv.x;
    o4.y = prev.y + d1 * scv.y * inv + ofv.y;
    o4.z = prev.z + d2 * scv.z * inv + ofv.z;
    o4.w = prev.w + d3 * scv.w * inv + ofv.w;
    *(float4*)orow = o4;
}

// ---------------- launcher ----------------
extern "C" void kernel_launch(void* const* d_in, const int* in_sizes, int n_in,
                              void* d_out, int out_size)
{
    const float* feat = (const float*)d_in[0];
    const float* vals = (const float*)d_in[1];
    const float* W0   = (const float*)d_in[2];
    const float* b0   = (const float*)d_in[3];
    const float* off0 = (const float*)d_in[4];
    const float* sc0  = (const float*)d_in[5];
    const float* W1   = (const float*)d_in[6];
    const float* b1   = (const float*)d_in[7];
    const float* off1 = (const float*)d_in[8];
    const float* sc1  = (const float*)d_in[9];
    const int*   rows = (const int*)d_in[10];
    const int*   cols = (const int*)d_in[11];
    float* out = (float*)d_out;

    const int smem = (128 * 128 + 64 * 128) * (int)sizeof(float); // 96 KB
    cudaFuncSetAttribute(gemm_kernel<true>,  cudaFuncAttributeMaxDynamicSharedMemorySize, smem);
    cudaFuncSetAttribute(gemm_kernel<false>, cudaFuncAttributeMaxDynamicSharedMemorySize, smem);

    // ---- CSR build (per replay; order-independent up to fp rounding) ----
    k_zero_deg<<<(NN + 255) / 256, 256>>>();
    k_hist<<<(EE + 255) / 256, 256>>>(rows);
    int nblk = (NN + 1023) / 1024;           // 98
    {
        int* offp;  cudaGetSymbolAddress((void**)&offp,  g_off);
        int* degp;  cudaGetSymbolAddress((void**)&degp,  g_deg);
        int* bsump; cudaGetSymbolAddress((void**)&bsump, g_bsum);
        k_scan_block<<<nblk, 1024>>>(degp, offp, bsump, NN);
        k_scan_block<<<1, 1024>>>(bsump, bsump, nullptr, nblk);
    }
    k_finalize_off<<<(NN + 255) / 256, 256>>>();
    k_scatter<<<(EE + 255) / 256, 256>>>(rows, cols, vals);

    // ---- dense part ----
    float* y1p; cudaGetSymbolAddress((void**)&y1p, g_y1);
    int gblocks = (NN + 63) / 64;
    gemm_kernel<true ><<<gblocks, 256, smem>>>(feat, W0, b0, off0, sc0, out, NN); // p0 -> out
    gemm_kernel<false><<<gblocks, 256, smem>>>(feat, W1, nullptr, nullptr, nullptr, y1p, NN); // y1

    // ---- sparse aggregate + fused p1 epilogue, out += p1 ----
    int sblocks = ((NN * 32) + 255) / 256;   // one warp per row
    spmm_kernel<<<sblocks, 256>>>(b1, off1, sc1, out);
}

// round 4
// speedup vs baseline: 1.1348x; 1.1348x over previous
#include <cuda_runtime.h>
#include <cuda_bf16.h>
#include <cstdint>

// Problem constants (fixed by the reference setup)
#define NN 100000
#define EE 3200000
#define GB 1563            // GEMM blocks per matrix: ceil(NN/64)

// ---------------- device scratch (no allocations allowed) ----------------
__device__ int   g_deg[NN];
__device__ int   g_off[NN];
__device__ int   g_cursor[NN];
__device__ int   g_bsum[1024];
__device__ uint2 g_epack[EE];               // (col, bits(w)) packed 8B
__device__ float g_y1[(size_t)NN * 128];    // feat @ W1

// ---------------- CSR build helpers ----------------
__global__ void k_zero_deg() {
    int i = blockIdx.x * blockDim.x + threadIdx.x;
    if (i < NN) g_deg[i] = 0;
}

__global__ void k_hist(const int* __restrict__ rows) {
    int e = blockIdx.x * blockDim.x + threadIdx.x;
    if (e < EE) atomicAdd(&g_deg[rows[e]], 1);
}

// block-level exclusive scan (1024 threads = 32 warps)
__global__ void k_scan_block(const int* __restrict__ in, int* __restrict__ out,
                             int* __restrict__ bsum, int n) {
    __shared__ int warpSums[32];
    int i = blockIdx.x * 1024 + threadIdx.x;
    int lane = threadIdx.x & 31, wid = threadIdx.x >> 5;
    int v = (i < n) ? in[i] : 0;
    int s = v;
    #pragma unroll
    for (int o = 1; o < 32; o <<= 1) {
        int t = __shfl_up_sync(0xffffffffu, s, o);
        if (lane >= o) s += t;
    }
    if (lane == 31) warpSums[wid] = s;
    __syncthreads();
    if (wid == 0) {
        int ws = warpSums[lane];
        #pragma unroll
        for (int o = 1; o < 32; o <<= 1) {
            int t = __shfl_up_sync(0xffffffffu, ws, o);
            if (lane >= o) ws += t;
        }
        warpSums[lane] = ws;
    }
    __syncthreads();
    int excl = s - v + ((wid > 0) ? warpSums[wid - 1] : 0);
    if (i < n) out[i] = excl;
    if (threadIdx.x == 1023 && bsum) bsum[blockIdx.x] = excl + v;
}

__global__ void k_finalize_off() {
    int i = blockIdx.x * blockDim.x + threadIdx.x;
    if (i < NN) {
        int o = g_off[i] + g_bsum[i >> 10];
        g_off[i] = o;
        g_cursor[i] = o;
    }
}

// ---------------- dense GEMM body: out = X[n,128] @ W[128,128] (+ fused epi) ----
// block = 256 threads = 8 warps; block tile = 64 rows; warp tile = 8 rows x 128 cols;
// lane owns cols [4*lane, 4*lane+4). (Round-1-proven fp32 FFMA body.)
template <bool EPI>
__device__ __forceinline__ void gemm_body(
    int blk, const float* __restrict__ X, const float* __restrict__ W,
    const float* __restrict__ b, const float* __restrict__ off,
    const float* __restrict__ sc, float* __restrict__ out, int n, float* smem)
{
    float* sW = smem;               // 128*128
    float* sX = smem + 128 * 128;   // 64*128

    const int warp = threadIdx.x >> 5, lane = threadIdx.x & 31;
    const int rowBase = blk * 64;

    // load W (16384 floats = 4096 float4, 16 per thread)
    for (int i = threadIdx.x; i < 128 * 32; i += 256)
        ((float4*)sW)[i] = ((const float4*)W)[i];
    // load X tile (64 rows, zero-pad tail)
    for (int i = threadIdx.x; i < 64 * 32; i += 256) {
        int r = i >> 5, kk = i & 31;
        float4 v = make_float4(0.f, 0.f, 0.f, 0.f);
        int gr = rowBase + r;
        if (gr < n) v = ((const float4*)(X + (size_t)gr * 128))[kk];
        ((float4*)sX)[i] = v;
    }
    __syncthreads();

    float acc[8][4];
    #pragma unroll
    for (int r = 0; r < 8; r++)
        #pragma unroll
        for (int c = 0; c < 4; c++) acc[r][c] = 0.f;

    const float* xbase = sX + (warp * 8) * 128;

    #pragma unroll 1
    for (int k = 0; k < 128; k += 4) {
        float4 wv0 = *(const float4*)(sW + (k + 0) * 128 + 4 * lane);
        float4 wv1 = *(const float4*)(sW + (k + 1) * 128 + 4 * lane);
        float4 wv2 = *(const float4*)(sW + (k + 2) * 128 + 4 * lane);
        float4 wv3 = *(const float4*)(sW + (k + 3) * 128 + 4 * lane);
        #pragma unroll
        for (int r = 0; r < 8; r++) {
            float4 xv = *(const float4*)(xbase + r * 128 + k);
            acc[r][0] = fmaf(xv.x, wv0.x, acc[r][0]);
            acc[r][1] = fmaf(xv.x, wv0.y, acc[r][1]);
            acc[r][2] = fmaf(xv.x, wv0.z, acc[r][2]);
            acc[r][3] = fmaf(xv.x, wv0.w, acc[r][3]);
            acc[r][0] = fmaf(xv.y, wv1.x, acc[r][0]);
            acc[r][1] = fmaf(xv.y, wv1.y, acc[r][1]);
            acc[r][2] = fmaf(xv.y, wv1.z, acc[r][2]);
            acc[r][3] = fmaf(xv.y, wv1.w, acc[r][3]);
            acc[r][0] = fmaf(xv.z, wv2.x, acc[r][0]);
            acc[r][1] = fmaf(xv.z, wv2.y, acc[r][1]);
            acc[r][2] = fmaf(xv.z, wv2.z, acc[r][2]);
            acc[r][3] = fmaf(xv.z, wv2.w, acc[r][3]);
            acc[r][0] = fmaf(xv.w, wv3.x, acc[r][0]);
            acc[r][1] = fmaf(xv.w, wv3.y, acc[r][1]);
            acc[r][2] = fmaf(xv.w, wv3.z, acc[r][2]);
            acc[r][3] = fmaf(xv.w, wv3.w, acc[r][3]);
        }
    }

    const int warpRow = rowBase + warp * 8;
    if (EPI) {
        float4 bv  = *(const float4*)(b  + 4 * lane);
        float4 scv = *(const float4*)(sc + 4 * lane);
        float4 ofv = *(const float4*)(off + 4 * lane);
        #pragma unroll
        for (int r = 0; r < 8; r++) {
            int row = warpRow + r;
            if (row >= n) break;
            float h0 = fmaxf(acc[r][0] + bv.x, 0.f);
            float h1 = fmaxf(acc[r][1] + bv.y, 0.f);
            float h2 = fmaxf(acc[r][2] + bv.z, 0.f);
            float h3 = fmaxf(acc[r][3] + bv.w, 0.f);
            float s = h0 + h1 + h2 + h3;
            #pragma unroll
            for (int o = 16; o; o >>= 1) s += __shfl_xor_sync(0xffffffffu, s, o);
            float mean = s * (1.f / 128.f);
            float d0 = h0 - mean, d1 = h1 - mean, d2 = h2 - mean, d3 = h3 - mean;
            float q = d0 * d0 + d1 * d1 + d2 * d2 + d3 * d3;
            #pragma unroll
            for (int o = 16; o; o >>= 1) q += __shfl_xor_sync(0xffffffffu, q, o);
            float inv = rsqrtf(q * (1.f / 128.f) + 1e-9f);
            float4 o4;
            o4.x = d0 * scv.x * inv + ofv.x;
            o4.y = d1 * scv.y * inv + ofv.y;
            o4.z = d2 * scv.z * inv + ofv.z;
            o4.w = d3 * scv.w * inv + ofv.w;
            *(float4*)(out + (size_t)row * 128 + 4 * lane) = o4;
        }
    } else {
        #pragma unroll
        for (int r = 0; r < 8; r++) {
            int row = warpRow + r;
            if (row >= n) break;
            float4 o4 = make_float4(acc[r][0], acc[r][1], acc[r][2], acc[r][3]);
            *(float4*)(out + (size_t)row * 128 + 4 * lane) = o4;
        }
    }
}

// ---------------- fused middle kernel: {gemm_p0, gemm_y1, scatter} concurrently ----
// 1:1 interleave: even blocks do one 64-row GEMM tile, odd blocks scatter 1024 edges.
// grid = 2 * 2 * GB = 6252 blocks. 2*GB*1024 = 3,201,024 >= EE.
__global__ __launch_bounds__(256) void fused_mid(
    const float* __restrict__ feat,
    const float* __restrict__ W0, const float* __restrict__ b0,
    const float* __restrict__ off0, const float* __restrict__ sc0,
    const float* __restrict__ W1,
    const int* __restrict__ rows, const int* __restrict__ cols,
    const float* __restrict__ vals,
    float* __restrict__ out, float* __restrict__ y1)
{
    extern __shared__ float smem[];
    int bid = blockIdx.x;
    int g = bid >> 1;
    if ((bid & 1) == 0) {
        if (g < GB) gemm_body<true >(g,      feat, W0, b0, off0, sc0, out, NN, smem);
        else        gemm_body<false>(g - GB, feat, W1, nullptr, nullptr, nullptr, y1, NN, smem);
    } else {
        int base = g * 1024 + (int)threadIdx.x;
        #pragma unroll
        for (int j = 0; j < 4; j++) {
            int e = base + j * 256;
            if (e < EE) {
                int rr = rows[e];
                int p = atomicAdd(&g_cursor[rr], 1);
                g_epack[p] = make_uint2((unsigned)cols[e], __float_as_uint(vals[e]));
            }
        }
    }
}

// ---------------- SpMM gather + fused epilogue: out[r] += norm(relu(A@y1 + b1)) ----
__global__ __launch_bounds__(256) void spmm_kernel(
    const float* __restrict__ b, const float* __restrict__ off,
    const float* __restrict__ sc, float* __restrict__ out)
{
    int gw = (blockIdx.x * blockDim.x + threadIdx.x) >> 5;
    if (gw >= NN) return;
    int lane = threadIdx.x & 31;
    int start = g_off[gw];
    int deg   = g_deg[gw];

    float4 acc = make_float4(0.f, 0.f, 0.f, 0.f);
    for (int base = 0; base < deg; base += 32) {
        int idx = base + lane;
        uint2 ew = make_uint2(0u, 0u);
        if (idx < deg) ew = g_epack[start + idx];
        int m = min(32, deg - base);
        #pragma unroll 4
        for (int j = 0; j < m; j++) {
            int   cj = (int)__shfl_sync(0xffffffffu, ew.x, j);
            float wj = __int_as_float(__shfl_sync(0xffffffffu, ew.y, j));
            float4 y = *(const float4*)(g_y1 + (size_t)cj * 128 + 4 * lane);
            acc.x = fmaf(wj, y.x, acc.x);
            acc.y = fmaf(wj, y.y, acc.y);
            acc.z = fmaf(wj, y.z, acc.z);
            acc.w = fmaf(wj, y.w, acc.w);
        }
    }

    float4 bv  = *(const float4*)(b  + 4 * lane);
    float4 scv = *(const float4*)(sc + 4 * lane);
    float4 ofv = *(const float4*)(off + 4 * lane);
    float h0 = fmaxf(acc.x + bv.x, 0.f);
    float h1 = fmaxf(acc.y + bv.y, 0.f);
    float h2 = fmaxf(acc.z + bv.z, 0.f);
    float h3 = fmaxf(acc.w + bv.w, 0.f);
    float s = h0 + h1 + h2 + h3;
    #pragma unroll
    for (int o = 16; o; o >>= 1) s += __shfl_xor_sync(0xffffffffu, s, o);
    float mean = s * (1.f / 128.f);
    float d0 = h0 - mean, d1 = h1 - mean, d2 = h2 - mean, d3 = h3 - mean;
    float q = d0 * d0 + d1 * d1 + d2 * d2 + d3 * d3;
    #pragma unroll
    for (int o = 16; o; o >>= 1) q += __shfl_xor_sync(0xffffffffu, q, o);
    float inv = rsqrtf(q * (1.f / 128.f) + 1e-9f);

    float* orow = out + (size_t)gw * 128 + 4 * lane;
    float4 prev = *(float4*)orow;
    float4 o4;
    o4.x = prev.x + d0 * scv.x * inv + ofv.x;
    o4.y = prev.y + d1 * scv.y * inv + ofv.y;
    o4.z = prev.z + d2 * scv.z * inv + ofv.z;
    o4.w = prev.w + d3 * scv.w * inv + ofv.w;
    *(float4*)orow = o4;
}

// ---------------- launcher ----------------
extern "C" void kernel_launch(void* const* d_in, const int* in_sizes, int n_in,
                              void* d_out, int out_size)
{
    const float* feat = (const float*)d_in[0];
    const float* vals = (const float*)d_in[1];
    const float* W0   = (const float*)d_in[2];
    const float* b0   = (const float*)d_in[3];
    const float* off0 = (const float*)d_in[4];
    const float* sc0  = (const float*)d_in[5];
    const float* W1   = (const float*)d_in[6];
    const float* b1   = (const float*)d_in[7];
    const float* off1 = (const float*)d_in[8];
    const float* sc1  = (const float*)d_in[9];
    const int*   rows = (const int*)d_in[10];
    const int*   cols = (const int*)d_in[11];
    float* out = (float*)d_out;

    const int smem = (128 * 128 + 64 * 128) * (int)sizeof(float); // 96 KB
    cudaFuncSetAttribute(fused_mid, cudaFuncAttributeMaxDynamicSharedMemorySize, smem);

    // ---- CSR front chain (serial, small) ----
    k_zero_deg<<<(NN + 255) / 256, 256>>>();
    k_hist<<<(EE + 255) / 256, 256>>>(rows);
    int nblk = (NN + 1023) / 1024;           // 98
    {
        int* offp;  cudaGetSymbolAddress((void**)&offp,  g_off);
        int* degp;  cudaGetSymbolAddress((void**)&degp,  g_deg);
        int* bsump; cudaGetSymbolAddress((void**)&bsump, g_bsum);
        k_scan_block<<<nblk, 1024>>>(degp, offp, bsump, NN);
        k_scan_block<<<1, 1024>>>(bsump, bsump, nullptr, nblk);
    }
    k_finalize_off<<<(NN + 255) / 256, 256>>>();

    // ---- fused middle: both GEMMs + edge scatter concurrently ----
    float* y1p; cudaGetSymbolAddress((void**)&y1p, g_y1);
    fused_mid<<<2 * 2 * GB, 256, smem>>>(feat, W0, b0, off0, sc0, W1,
                                         rows, cols, vals, out, y1p);

    // ---- sparse aggregate + fused p1 epilogue, out += p1 ----
    int sblocks = ((NN * 32) + 255) / 256;   // one warp per row
    spmm_kernel<<<sblocks, 256>>>(b1, off1, sc1, out);
}